// round 2
// baseline (speedup 1.0000x reference)
#include <cuda_runtime.h>
#include <cuda_bf16.h>

#define Nn   100000
#define Ee   1600000
#define FIN  50
#define HD   64
#define NG   512
#define NC   10
#define BOND 10

// ---------------- scratch (device globals; no allocation allowed) ----------------
__device__ __align__(16) float g_ew[Ee];
__device__ __align__(16) float g_agg1[Nn * FIN];
__device__ __align__(16) float g_h1[Nn * HD];     // relu(h1), input to conv2
__device__ __align__(16) float g_agg2[Nn * HD];
__device__ __align__(16) float g_max1[NG * HD];
__device__ __align__(16) float g_max2[NG * HD];
__device__ __align__(16) float g_sumv[NG * HD];   // combined sum pool (h1 + h2)
__device__ __align__(16) float g_cnt[NG];

// float atomic max via int/uint ordering trick
__device__ __forceinline__ void atomicMaxF(float* a, float v) {
    if (v >= 0.f) atomicMax((int*)a, __float_as_int(v));
    else          atomicMin((unsigned int*)a, __float_as_uint(v));
}

// ---------------- init: zero accumulators, -inf maxes ----------------
__global__ void k_init() {
    int i = blockIdx.x * blockDim.x + threadIdx.x;
    int stride = gridDim.x * blockDim.x;
    for (int j = i; j < Nn * FIN; j += stride) g_agg1[j] = 0.f;
    for (int j = i; j < Nn * HD;  j += stride) g_agg2[j] = 0.f;
    float ninf = __int_as_float(0xff800000);
    for (int j = i; j < NG * HD;  j += stride) {
        g_sumv[j] = 0.f; g_max1[j] = ninf; g_max2[j] = ninf;
    }
    for (int j = i; j < NG; j += stride) g_cnt[j] = 0.f;
}

// ---------------- edge weights: ew = edge_a @ bond_w.T + bond_b ----------------
__global__ void k_ew(const float* __restrict__ ea,
                     const float* __restrict__ bw,
                     const float* __restrict__ bb) {
    int e = blockIdx.x * blockDim.x + threadIdx.x;
    if (e >= Ee) return;
    const float* row = ea + (size_t)e * BOND;
    float s = bb[0];
#pragma unroll
    for (int j = 0; j < BOND; j++) s += row[j] * __ldg(&bw[j]);
    g_ew[e] = s;
}

// ---------------- conv1 scatter: agg1[dst] += ew * x[src]  (warp per edge) ------
__global__ void k_scatter1(const float* __restrict__ x,
                           const int* __restrict__ ei) {
    int tid  = blockIdx.x * blockDim.x + threadIdx.x;
    int e    = tid >> 5;
    int lane = tid & 31;
    if (e >= Ee) return;
    int s = ei[e];
    int d = ei[Ee + e];
    float w = g_ew[e];
    if (lane < 25) {   // 25 float2 = 50 floats, rows are 8B aligned
        const float2* xs = (const float2*)(x + (size_t)s * FIN);
        float2 v = xs[lane];
        float* dptr = g_agg1 + (size_t)d * FIN + lane * 2;
        asm volatile("red.global.add.v2.f32 [%0], {%1,%2};"
                     :: "l"(dptr), "f"(v.x * w), "f"(v.y * w) : "memory");
    }
}

// ---------------- conv2 scatter: agg2[dst] += ew * h1[src] (half-warp per edge) -
__global__ void k_scatter2(const int* __restrict__ ei) {
    int tid  = blockIdx.x * blockDim.x + threadIdx.x;
    int e    = tid >> 4;
    int lane = tid & 15;
    if (e >= Ee) return;
    int s = ei[e];
    int d = ei[Ee + e];
    float w = g_ew[e];
    const float4* hs = (const float4*)(g_h1 + (size_t)s * HD);
    float4 v = hs[lane];
    float* dptr = g_agg2 + (size_t)d * HD + lane * 4;
    asm volatile("red.global.add.v4.f32 [%0], {%1,%2,%3,%4};"
                 :: "l"(dptr), "f"(v.x * w), "f"(v.y * w),
                    "f"(v.z * w), "f"(v.w * w) : "memory");
}

// ---------------- conv1 post: h = agg1@rel.T + b + x@root.T, pool1, relu --------
__global__ void k_conv1(const float* __restrict__ x,
                        const float* __restrict__ relw,
                        const float* __restrict__ relb,
                        const float* __restrict__ rootw,
                        const int* __restrict__ batch) {
    __shared__ float wr[HD][FIN + 1];
    __shared__ float wo[HD][FIN + 1];
    int tid = threadIdx.x;
    for (int idx = tid; idx < HD * FIN; idx += 256) {
        int o = idx / FIN, k = idx % FIN;
        wr[o][k] = relw[idx];
        wo[o][k] = rootw[idx];
    }
    __syncthreads();
    int o   = tid & 63;
    int sub = tid >> 6;            // 0..3
    float bias = relb[o];
    int base = blockIdx.x * 128;
    for (int i = 0; i < 32; i++) {
        int n = base + sub * 32 + i;
        if (n >= Nn) break;
        const float* a  = g_agg1 + (size_t)n * FIN;
        const float* xr = x + (size_t)n * FIN;
        float s = bias;
#pragma unroll
        for (int k = 0; k < FIN; k++) s += a[k] * wr[o][k] + xr[k] * wo[o][k];
        int b = batch[n];
        atomicAdd(&g_sumv[b * HD + o], s);
        atomicMaxF(&g_max1[b * HD + o], s);
        if (o == 0) atomicAdd(&g_cnt[b], 1.0f);
        g_h1[(size_t)n * HD + o] = fmaxf(s, 0.f);
    }
}

// ---------------- conv2 post: h2 = agg2@rel.T + b + h1r@root.T, pool2 -----------
__global__ void k_conv2(const float* __restrict__ relw,
                        const float* __restrict__ relb,
                        const float* __restrict__ rootw,
                        const int* __restrict__ batch) {
    __shared__ float wr[HD][HD + 1];
    __shared__ float wo[HD][HD + 1];
    int tid = threadIdx.x;
    for (int idx = tid; idx < HD * HD; idx += 256) {
        int o = idx / HD, k = idx % HD;
        wr[o][k] = relw[idx];
        wo[o][k] = rootw[idx];
    }
    __syncthreads();
    int o   = tid & 63;
    int sub = tid >> 6;
    float bias = relb[o];
    int base = blockIdx.x * 128;
    for (int i = 0; i < 32; i++) {
        int n = base + sub * 32 + i;
        if (n >= Nn) break;
        const float* a  = g_agg2 + (size_t)n * HD;
        const float* hr = g_h1 + (size_t)n * HD;
        float s = bias;
#pragma unroll
        for (int k = 0; k < HD; k++) s += a[k] * wr[o][k] + hr[k] * wo[o][k];
        int b = batch[n];
        atomicAdd(&g_sumv[b * HD + o], s);
        atomicMaxF(&g_max2[b * HD + o], s);
    }
}

// ---------------- head: g = [max1+max2 | sum/cnt]; relu(g@W1.T+b1)@W2.T+b2 ------
__global__ void k_head(const float* __restrict__ l1w, const float* __restrict__ l1b,
                       const float* __restrict__ l2w, const float* __restrict__ l2b,
                       float* __restrict__ out) {
    int g = blockIdx.x;
    __shared__ float gv[2 * HD];
    __shared__ float av[HD];
    int t = threadIdx.x;   // 128 threads
    if (t < HD) {
        gv[t] = g_max1[g * HD + t] + g_max2[g * HD + t];
    } else {
        float c = g_cnt[g];
        gv[t] = g_sumv[g * HD + (t - HD)] / fmaxf(c, 1.0f);
    }
    __syncthreads();
    if (t < HD) {
        float s = l1b[t];
        const float* w = l1w + t * 2 * HD;
#pragma unroll
        for (int k = 0; k < 2 * HD; k++) s += gv[k] * w[k];
        av[t] = fmaxf(s, 0.f);
    }
    __syncthreads();
    if (t < NC) {
        float s = l2b[t];
        const float* w = l2w + t * HD;
#pragma unroll
        for (int k = 0; k < HD; k++) s += av[k] * w[k];
        out[g * NC + t] = s;
    }
}

extern "C" void kernel_launch(void* const* d_in, const int* in_sizes, int n_in,
                              void* d_out, int out_size) {
    const float* x           = (const float*)d_in[0];
    const float* edge_a      = (const float*)d_in[1];
    const float* bond_w      = (const float*)d_in[2];
    const float* bond_b      = (const float*)d_in[3];
    const float* c1_rel_w    = (const float*)d_in[4];
    const float* c1_rel_b    = (const float*)d_in[5];
    const float* c1_root_w   = (const float*)d_in[6];
    const float* c2_rel_w    = (const float*)d_in[7];
    const float* c2_rel_b    = (const float*)d_in[8];
    const float* c2_root_w   = (const float*)d_in[9];
    const float* lin1_w      = (const float*)d_in[10];
    const float* lin1_b      = (const float*)d_in[11];
    const float* lin2_w      = (const float*)d_in[12];
    const float* lin2_b      = (const float*)d_in[13];
    const int*   edge_ix     = (const int*)d_in[14];   // int32! (JAX x64 disabled)
    const int*   batch       = (const int*)d_in[15];   // int32!
    float* out = (float*)d_out;

    k_init<<<2048, 256>>>();
    k_ew<<<(Ee + 255) / 256, 256>>>(edge_a, bond_w, bond_b);
    k_scatter1<<<Ee / 8, 256>>>(x, edge_ix);                 // warp per edge
    k_conv1<<<(Nn + 127) / 128, 256>>>(x, c1_rel_w, c1_rel_b, c1_root_w, batch);
    k_scatter2<<<Ee / 16, 256>>>(edge_ix);                   // half-warp per edge
    k_conv2<<<(Nn + 127) / 128, 256>>>(c2_rel_w, c2_rel_b, c2_root_w, batch);
    k_head<<<NG, 128>>>(lin1_w, lin1_b, lin2_w, lin2_b, out);
}

// round 3
// speedup vs baseline: 1.4154x; 1.4154x over previous
#include <cuda_runtime.h>
#include <cuda_bf16.h>

#define Nn   100000
#define Ee   1600000
#define FIN  50
#define HD   64
#define NG   512
#define NC   10
#define BOND 10

// ---------------- scratch (device globals; no allocation allowed) ----------------
__device__ __align__(16) float g_ew[Ee];
__device__ __align__(16) float g_agg1[Nn * FIN];
__device__ __align__(16) float g_h1[Nn * HD];     // relu(h1), input to conv2
__device__ __align__(16) float g_agg2[Nn * HD];
__device__ __align__(16) float g_max1[NG * HD];
__device__ __align__(16) float g_max2[NG * HD];
__device__ __align__(16) float g_sumv[NG * HD];   // combined sum pool (h1 + h2)
__device__ __align__(16) float g_cnt[NG];

__device__ __forceinline__ void atomicMaxF(float* a, float v) {
    if (v >= 0.f) atomicMax((int*)a, __float_as_int(v));
    else          atomicMin((unsigned int*)a, __float_as_uint(v));
}

// ---------------- init ----------------
__global__ void k_init() {
    int i = blockIdx.x * blockDim.x + threadIdx.x;
    int stride = gridDim.x * blockDim.x;
    for (int j = i; j < Nn * FIN; j += stride) g_agg1[j] = 0.f;
    for (int j = i; j < Nn * HD;  j += stride) g_agg2[j] = 0.f;
    float ninf = __int_as_float(0xff800000);
    for (int j = i; j < NG * HD;  j += stride) {
        g_sumv[j] = 0.f; g_max1[j] = ninf; g_max2[j] = ninf;
    }
    for (int j = i; j < NG; j += stride) g_cnt[j] = 0.f;
}

// ---------------- edge weights ----------------
__global__ void k_ew(const float* __restrict__ ea,
                     const float* __restrict__ bw,
                     const float* __restrict__ bb) {
    int e = blockIdx.x * blockDim.x + threadIdx.x;
    if (e >= Ee) return;
    const float2* row = (const float2*)(ea + (size_t)e * BOND);
    float s = bb[0];
#pragma unroll
    for (int j = 0; j < BOND / 2; j++) {
        float2 v = row[j];
        s += v.x * __ldg(&bw[2 * j]) + v.y * __ldg(&bw[2 * j + 1]);
    }
    g_ew[e] = s;
}

// ---------------- conv1 scatter: agg1[dst] += ew * x[src]  (warp per edge) ------
__global__ void k_scatter1(const float* __restrict__ x,
                           const int* __restrict__ ei) {
    int tid  = blockIdx.x * blockDim.x + threadIdx.x;
    int e    = tid >> 5;
    int lane = tid & 31;
    if (e >= Ee) return;
    int s = ei[e];
    int d = ei[Ee + e];
    float w = g_ew[e];
    if (lane < 25) {
        const float2* xs = (const float2*)(x + (size_t)s * FIN);
        float2 v = xs[lane];
        float* dptr = g_agg1 + (size_t)d * FIN + lane * 2;
        asm volatile("red.global.add.v2.f32 [%0], {%1,%2};"
                     :: "l"(dptr), "f"(v.x * w), "f"(v.y * w) : "memory");
    }
}

// ---------------- conv2 scatter: agg2[dst] += ew * h1[src] (half-warp per edge) -
__global__ void k_scatter2(const int* __restrict__ ei) {
    int tid  = blockIdx.x * blockDim.x + threadIdx.x;
    int e    = tid >> 4;
    int lane = tid & 15;
    if (e >= Ee) return;
    int s = ei[e];
    int d = ei[Ee + e];
    float w = g_ew[e];
    const float4* hs = (const float4*)(g_h1 + (size_t)s * HD);
    float4 v = hs[lane];
    float* dptr = g_agg2 + (size_t)d * HD + lane * 4;
    asm volatile("red.global.add.v4.f32 [%0], {%1,%2,%3,%4};"
                 :: "l"(dptr), "f"(v.x * w), "f"(v.y * w),
                    "f"(v.z * w), "f"(v.w * w) : "memory");
}

// ============== fused conv: C[N x 64] = [agg | other] @ [relw | rootw]^T + relb
// Block: 128 nodes, 256 threads = 32 o-pairs x 8 node-slots (16 nodes each).
// IS_CONV1: sources g_agg1 + x (K=100). else g_agg2 + g_h1 (K=128).
template<int K, int CHUNK, bool IS_CONV1>
__global__ void k_conv(const float* __restrict__ xin,   // x for conv1, unused conv2
                       const float* __restrict__ relw,
                       const float* __restrict__ relb,
                       const float* __restrict__ rootw,
                       const int* __restrict__ batch,
                       float* __restrict__ gmax) {
    constexpr int KH = K / 2;
    __shared__ float vs[CHUNK][132];   // [k][node], padded (float4-aligned rows)
    __shared__ float ws[CHUNK][64];    // [k][o]

    int tid  = threadIdx.x;
    int o    = tid & 31;               // outputs o and o+32
    int slot = tid >> 5;               // 0..7 -> nodes slot*16 .. slot*16+15
    int base = blockIdx.x * 128;

    float acc0[16], acc1[16];
    float b0 = relb[o], b1 = relb[o + 32];
#pragma unroll
    for (int j = 0; j < 16; j++) { acc0[j] = b0; acc1[j] = b1; }

#pragma unroll 1
    for (int kc = 0; kc < K; kc += CHUNK) {
        // stage weights: ws[k][oo] = W[oo][kc+k]
        for (int idx = tid; idx < CHUNK * 64; idx += 256) {
            int k = idx >> 6, oo = idx & 63;
            int kk = kc + k;
            float w = (kk < KH) ? relw[oo * KH + kk] : rootw[oo * KH + (kk - KH)];
            ws[k][oo] = w;
        }
        // stage values transposed: vs[k][n] = A[base+n][kc+k]
        for (int idx = tid; idx < CHUNK * 128; idx += 256) {
            int n = idx / CHUNK, k = idx % CHUNK;
            int gn = base + n;
            int kk = kc + k;
            float v = 0.f;
            if (gn < Nn) {
                if (IS_CONV1) {
                    v = (kk < KH) ? g_agg1[(size_t)gn * KH + kk]
                                  : xin[(size_t)gn * KH + (kk - KH)];
                } else {
                    v = (kk < KH) ? g_agg2[(size_t)gn * KH + kk]
                                  : g_h1[(size_t)gn * KH + (kk - KH)];
                }
            }
            vs[k][n] = v;
        }
        __syncthreads();
#pragma unroll
        for (int k = 0; k < CHUNK; k++) {
            float w0 = ws[k][o];
            float w1 = ws[k][o + 32];
            const float4* vrow = (const float4*)&vs[k][slot * 16];
#pragma unroll
            for (int q = 0; q < 4; q++) {
                float4 v4 = vrow[q];
                acc0[q*4+0] += w0 * v4.x; acc1[q*4+0] += w1 * v4.x;
                acc0[q*4+1] += w0 * v4.y; acc1[q*4+1] += w1 * v4.y;
                acc0[q*4+2] += w0 * v4.z; acc1[q*4+2] += w1 * v4.z;
                acc0[q*4+3] += w0 * v4.w; acc1[q*4+3] += w1 * v4.w;
            }
        }
        __syncthreads();
    }

    // epilogue: pooling with run-length flush (batch is sorted), optional h write
    float ninf = __int_as_float(0xff800000);
    float rs0 = 0.f, rs1 = 0.f, rm0 = ninf, rm1 = ninf;
    int runb = -1, runcnt = 0;
    int nb = base + slot * 16;
#pragma unroll 1
    for (int j = 0; j < 16; j++) {
        int n = nb + j;
        if (n >= Nn) break;
        float s0 = acc0[j], s1 = acc1[j];
        int b = batch[n];
        if (b != runb) {
            if (runb >= 0) {
                atomicAdd(&g_sumv[runb * HD + o], rs0);
                atomicAdd(&g_sumv[runb * HD + o + 32], rs1);
                atomicMaxF(&gmax[runb * HD + o], rm0);
                atomicMaxF(&gmax[runb * HD + o + 32], rm1);
                if (IS_CONV1 && o == 0) atomicAdd(&g_cnt[runb], (float)runcnt);
            }
            runb = b; rs0 = 0.f; rs1 = 0.f; rm0 = ninf; rm1 = ninf; runcnt = 0;
        }
        rs0 += s0; rs1 += s1;
        rm0 = fmaxf(rm0, s0); rm1 = fmaxf(rm1, s1);
        runcnt++;
        if (IS_CONV1) {
            g_h1[(size_t)n * HD + o]      = fmaxf(s0, 0.f);
            g_h1[(size_t)n * HD + o + 32] = fmaxf(s1, 0.f);
        }
    }
    if (runb >= 0) {
        atomicAdd(&g_sumv[runb * HD + o], rs0);
        atomicAdd(&g_sumv[runb * HD + o + 32], rs1);
        atomicMaxF(&gmax[runb * HD + o], rm0);
        atomicMaxF(&gmax[runb * HD + o + 32], rm1);
        if (IS_CONV1 && o == 0) atomicAdd(&g_cnt[runb], (float)runcnt);
    }
}

// ---------------- head ----------------
__global__ void k_head(const float* __restrict__ l1w, const float* __restrict__ l1b,
                       const float* __restrict__ l2w, const float* __restrict__ l2b,
                       float* __restrict__ out) {
    int g = blockIdx.x;
    __shared__ float gv[2 * HD];
    __shared__ float av[HD];
    int t = threadIdx.x;   // 128 threads
    if (t < HD) {
        gv[t] = g_max1[g * HD + t] + g_max2[g * HD + t];
    } else {
        float c = g_cnt[g];
        gv[t] = g_sumv[g * HD + (t - HD)] / fmaxf(c, 1.0f);
    }
    __syncthreads();
    if (t < HD) {
        float s = l1b[t];
        const float* w = l1w + t * 2 * HD;
#pragma unroll
        for (int k = 0; k < 2 * HD; k++) s += gv[k] * w[k];
        av[t] = fmaxf(s, 0.f);
    }
    __syncthreads();
    if (t < NC) {
        float s = l2b[t];
        const float* w = l2w + t * HD;
#pragma unroll
        for (int k = 0; k < HD; k++) s += av[k] * w[k];
        out[g * NC + t] = s;
    }
}

extern "C" void kernel_launch(void* const* d_in, const int* in_sizes, int n_in,
                              void* d_out, int out_size) {
    const float* x           = (const float*)d_in[0];
    const float* edge_a      = (const float*)d_in[1];
    const float* bond_w      = (const float*)d_in[2];
    const float* bond_b      = (const float*)d_in[3];
    const float* c1_rel_w    = (const float*)d_in[4];
    const float* c1_rel_b    = (const float*)d_in[5];
    const float* c1_root_w   = (const float*)d_in[6];
    const float* c2_rel_w    = (const float*)d_in[7];
    const float* c2_rel_b    = (const float*)d_in[8];
    const float* c2_root_w   = (const float*)d_in[9];
    const float* lin1_w      = (const float*)d_in[10];
    const float* lin1_b      = (const float*)d_in[11];
    const float* lin2_w      = (const float*)d_in[12];
    const float* lin2_b      = (const float*)d_in[13];
    const int*   edge_ix     = (const int*)d_in[14];   // int32
    const int*   batch       = (const int*)d_in[15];   // int32

    float* out = (float*)d_out;
    float* gmax1; cudaGetSymbolAddress((void**)&gmax1, g_max1);
    float* gmax2; cudaGetSymbolAddress((void**)&gmax2, g_max2);

    k_init<<<2048, 256>>>();
    k_ew<<<(Ee + 255) / 256, 256>>>(edge_a, bond_w, bond_b);
    k_scatter1<<<Ee / 8, 256>>>(x, edge_ix);
    k_conv<100, 25, true><<<(Nn + 127) / 128, 256>>>(
        x, c1_rel_w, c1_rel_b, c1_root_w, batch, gmax1);
    k_scatter2<<<Ee / 16, 256>>>(edge_ix);
    k_conv<128, 32, false><<<(Nn + 127) / 128, 256>>>(
        nullptr, c2_rel_w, c2_rel_b, c2_root_w, batch, gmax2);
    k_head<<<NG, 128>>>(lin1_w, lin1_b, lin2_w, lin2_b, out);
}

// round 4
// speedup vs baseline: 2.1277x; 1.5032x over previous
#include <cuda_runtime.h>
#include <cuda_bf16.h>

#define Nn   100000
#define Ee   1600000
#define FIN  50
#define HD   64
#define NG   512
#define NC   10
#define BOND 10
#define NBLK 391          // ceil(Nn/256)

// ---------------- scratch (device globals) ----------------
__device__ __align__(16) int   g_deg[Nn];        // histogram / scratch
__device__ __align__(16) int   g_rowx[Nn];       // block-local exclusive scan
__device__ __align__(16) int   g_bsum[NBLK];
__device__ __align__(16) int   g_topex[512];
__device__ __align__(16) int   g_row[Nn + 1];    // CSR row starts
__device__ __align__(16) int   g_cur[Nn];        // placement cursors
__device__ __align__(16) int2  g_epk[Ee];        // packed (src, ew-bits), dst-sorted
__device__ __align__(16) float g_h1[Nn * HD];    // relu(h1)
__device__ __align__(16) float g_max1[NG * HD];
__device__ __align__(16) float g_max2[NG * HD];
__device__ __align__(16) float g_sumv[NG * HD];
__device__ __align__(16) float g_cnt[NG];

__device__ __forceinline__ void atomicMaxF(float* a, float v) {
    if (v >= 0.f) atomicMax((int*)a, __float_as_int(v));
    else          atomicMin((unsigned int*)a, __float_as_uint(v));
}

// ---------------- init: zero histogram + pool accumulators ----------------
__global__ void k_init0() {
    int i = blockIdx.x * blockDim.x + threadIdx.x;
    int stride = gridDim.x * blockDim.x;
    for (int j = i; j < Nn; j += stride) g_deg[j] = 0;
    float ninf = __int_as_float(0xff800000);
    for (int j = i; j < NG * HD; j += stride) {
        g_sumv[j] = 0.f; g_max1[j] = ninf; g_max2[j] = ninf;
    }
    for (int j = i; j < NG; j += stride) g_cnt[j] = 0.f;
}

// ---------------- histogram of dst ----------------
__global__ void k_hist(const int* __restrict__ ei) {
    int e = blockIdx.x * blockDim.x + threadIdx.x;
    if (e >= Ee) return;
    atomicAdd(&g_deg[ei[Ee + e]], 1);
}

// ---------------- hierarchical exclusive scan of g_deg ----------------
__global__ void k_scan_block() {
    __shared__ int s[256];
    int t = threadIdx.x;
    int i = blockIdx.x * 256 + t;
    int v = (i < Nn) ? g_deg[i] : 0;
    s[t] = v;
    __syncthreads();
#pragma unroll
    for (int off = 1; off < 256; off <<= 1) {
        int x = (t >= off) ? s[t - off] : 0;
        __syncthreads();
        s[t] += x;
        __syncthreads();
    }
    if (i < Nn) g_rowx[i] = s[t] - v;          // exclusive
    if (t == 255) g_bsum[blockIdx.x] = s[t];   // block total
}

__global__ void k_scan_top() {
    __shared__ int s[512];
    int t = threadIdx.x;
    int v = (t < NBLK) ? g_bsum[t] : 0;
    s[t] = v;
    __syncthreads();
#pragma unroll
    for (int off = 1; off < 512; off <<= 1) {
        int x = (t >= off) ? s[t - off] : 0;
        __syncthreads();
        s[t] += x;
        __syncthreads();
    }
    g_topex[t] = s[t] - v;                     // exclusive
}

__global__ void k_scan_add() {
    int i = blockIdx.x * blockDim.x + threadIdx.x;
    if (i == 0) g_row[Nn] = Ee;
    if (i >= Nn) return;
    int rs = g_rowx[i] + g_topex[i >> 8];
    g_row[i] = rs;
    g_cur[i] = rs;
}

// ---------------- permute: compute ew inline, place (src, ew) sorted by dst ----
__global__ void k_permute(const int* __restrict__ ei,
                          const float* __restrict__ ea,
                          const float* __restrict__ bw,
                          const float* __restrict__ bb) {
    int e = blockIdx.x * blockDim.x + threadIdx.x;
    if (e >= Ee) return;
    const float2* row = (const float2*)(ea + (size_t)e * BOND);
    float w = bb[0];
#pragma unroll
    for (int j = 0; j < BOND / 2; j++) {
        float2 v = row[j];
        w += v.x * __ldg(&bw[2 * j]) + v.y * __ldg(&bw[2 * j + 1]);
    }
    int s = ei[e];
    int d = ei[Ee + e];
    int pos = atomicAdd(&g_cur[d], 1);
    g_epk[pos] = make_int2(s, __float_as_int(w));
}

// ============== fused conv layer ==============
// 512 threads, 128-node tile. Phase A: warp-per-8-nodes CSR gather-reduce of
// src rows into transposed smem vs[k][n] (no atomics, no global agg).
// Phase B: C = vs^T @ relw^T + rows(src) @ rootw^T + b, 2 outs x 8 nodes/thread.
// Epilogue: run-length pooling (batch sorted) + (conv1) relu h1 store.
// KH = half-K = row width of src (50 or 64). NL = KH/2 float2 lanes.
template<int KH, bool IS_CONV1>
__global__ __launch_bounds__(512, 3)
void k_conv_fused(const float* __restrict__ src,     // x (conv1) or g_h1 (conv2)
                  const float* __restrict__ relw,
                  const float* __restrict__ relb,
                  const float* __restrict__ rootw,
                  const int* __restrict__ batch,
                  float* __restrict__ gmax) {
    constexpr int NL = KH / 2;
    extern __shared__ float smem[];
    float* vs = smem;                 // [KH][132]
    float* ws = smem + KH * 132;      // [KH][64]

    int tid  = threadIdx.x;
    int lane = tid & 31;
    int wid  = tid >> 5;              // 0..15
    int o    = lane;                  // outputs o, o+32
    int slot = wid;                   // 8 nodes per slot
    int base = blockIdx.x * 128;

    // ---- stage rel weights (ws[k][oo] = relw[oo][k]) ----
    for (int idx = tid; idx < KH * 64; idx += 512) {
        int oo = idx & 63, k = idx >> 6;
        ws[k * 64 + oo] = relw[oo * KH + k];
    }

    // ---- phase A: gather-reduce agg rows into vs (transposed) ----
#pragma unroll 1
    for (int j = 0; j < 8; j++) {
        int n = base + wid * 8 + j;
        float2 acc = make_float2(0.f, 0.f);
        if (n < Nn) {
            int e0 = g_row[n], e1 = g_row[n + 1];
#pragma unroll 1
            for (int e = e0; e < e1; e++) {
                int2 p = __ldg(&g_epk[e]);
                float w = __int_as_float(p.y);
                if (lane < NL) {
                    float2 v = ((const float2*)(src + (size_t)p.x * KH))[lane];
                    acc.x += w * v.x;
                    acc.y += w * v.y;
                }
            }
        }
        if (lane < NL) {
            int nn = wid * 8 + j;
            vs[(2 * lane) * 132 + nn]     = acc.x;
            vs[(2 * lane + 1) * 132 + nn] = acc.y;
        }
    }
    __syncthreads();

    // ---- phase B chunk 1: rel part ----
    float acc0[8], acc1[8];
    float b0 = relb[o], b1 = relb[o + 32];
#pragma unroll
    for (int j = 0; j < 8; j++) { acc0[j] = b0; acc1[j] = b1; }

#pragma unroll 8
    for (int k = 0; k < KH; k++) {
        float w0 = ws[k * 64 + o];
        float w1 = ws[k * 64 + o + 32];
        float4 a = *(const float4*)&vs[k * 132 + slot * 8];
        float4 b = *(const float4*)&vs[k * 132 + slot * 8 + 4];
        acc0[0] += w0 * a.x; acc1[0] += w1 * a.x;
        acc0[1] += w0 * a.y; acc1[1] += w1 * a.y;
        acc0[2] += w0 * a.z; acc1[2] += w1 * a.z;
        acc0[3] += w0 * a.w; acc1[3] += w1 * a.w;
        acc0[4] += w0 * b.x; acc1[4] += w1 * b.x;
        acc0[5] += w0 * b.y; acc1[5] += w1 * b.y;
        acc0[6] += w0 * b.z; acc1[6] += w1 * b.z;
        acc0[7] += w0 * b.w; acc1[7] += w1 * b.w;
    }
    __syncthreads();

    // ---- restage: vs <- src rows (coalesced), ws <- root weights ----
    for (int idx = tid; idx < 128 * NL; idx += 512) {
        int n = idx / NL, i = idx % NL;
        float2 v = make_float2(0.f, 0.f);
        if (base + n < Nn)
            v = ((const float2*)(src + (size_t)(base + n) * KH))[i];
        vs[(2 * i) * 132 + n]     = v.x;
        vs[(2 * i + 1) * 132 + n] = v.y;
    }
    for (int idx = tid; idx < KH * 64; idx += 512) {
        int oo = idx & 63, k = idx >> 6;
        ws[k * 64 + oo] = rootw[oo * KH + k];
    }
    __syncthreads();

    // ---- phase B chunk 2: root part ----
#pragma unroll 8
    for (int k = 0; k < KH; k++) {
        float w0 = ws[k * 64 + o];
        float w1 = ws[k * 64 + o + 32];
        float4 a = *(const float4*)&vs[k * 132 + slot * 8];
        float4 b = *(const float4*)&vs[k * 132 + slot * 8 + 4];
        acc0[0] += w0 * a.x; acc1[0] += w1 * a.x;
        acc0[1] += w0 * a.y; acc1[1] += w1 * a.y;
        acc0[2] += w0 * a.z; acc1[2] += w1 * a.z;
        acc0[3] += w0 * a.w; acc1[3] += w1 * a.w;
        acc0[4] += w0 * b.x; acc1[4] += w1 * b.x;
        acc0[5] += w0 * b.y; acc1[5] += w1 * b.y;
        acc0[6] += w0 * b.z; acc1[6] += w1 * b.z;
        acc0[7] += w0 * b.w; acc1[7] += w1 * b.w;
    }

    // ---- epilogue: run-length pooling + (conv1) h1 store ----
    float ninf = __int_as_float(0xff800000);
    float rs0 = 0.f, rs1 = 0.f, rm0 = ninf, rm1 = ninf;
    int runb = -1, runcnt = 0;
    int nb = base + slot * 8;
#pragma unroll 1
    for (int j = 0; j < 8; j++) {
        int n = nb + j;
        if (n >= Nn) break;
        float s0 = acc0[j], s1 = acc1[j];
        int b = batch[n];
        if (b != runb) {
            if (runb >= 0) {
                atomicAdd(&g_sumv[runb * HD + o], rs0);
                atomicAdd(&g_sumv[runb * HD + o + 32], rs1);
                atomicMaxF(&gmax[runb * HD + o], rm0);
                atomicMaxF(&gmax[runb * HD + o + 32], rm1);
                if (IS_CONV1 && o == 0) atomicAdd(&g_cnt[runb], (float)runcnt);
            }
            runb = b; rs0 = 0.f; rs1 = 0.f; rm0 = ninf; rm1 = ninf; runcnt = 0;
        }
        rs0 += s0; rs1 += s1;
        rm0 = fmaxf(rm0, s0); rm1 = fmaxf(rm1, s1);
        runcnt++;
        if (IS_CONV1) {
            g_h1[(size_t)n * HD + o]      = fmaxf(s0, 0.f);
            g_h1[(size_t)n * HD + o + 32] = fmaxf(s1, 0.f);
        }
    }
    if (runb >= 0) {
        atomicAdd(&g_sumv[runb * HD + o], rs0);
        atomicAdd(&g_sumv[runb * HD + o + 32], rs1);
        atomicMaxF(&gmax[runb * HD + o], rm0);
        atomicMaxF(&gmax[runb * HD + o + 32], rm1);
        if (IS_CONV1 && o == 0) atomicAdd(&g_cnt[runb], (float)runcnt);
    }
}

// ---------------- head ----------------
__global__ void k_head(const float* __restrict__ l1w, const float* __restrict__ l1b,
                       const float* __restrict__ l2w, const float* __restrict__ l2b,
                       float* __restrict__ out) {
    int g = blockIdx.x;
    __shared__ float gv[2 * HD];
    __shared__ float av[HD];
    int t = threadIdx.x;   // 128
    if (t < HD) {
        gv[t] = g_max1[g * HD + t] + g_max2[g * HD + t];
    } else {
        float c = g_cnt[g];
        gv[t] = g_sumv[g * HD + (t - HD)] / fmaxf(c, 1.0f);
    }
    __syncthreads();
    if (t < HD) {
        float s = l1b[t];
        const float* w = l1w + t * 2 * HD;
#pragma unroll
        for (int k = 0; k < 2 * HD; k++) s += gv[k] * w[k];
        av[t] = fmaxf(s, 0.f);
    }
    __syncthreads();
    if (t < NC) {
        float s = l2b[t];
        const float* w = l2w + t * HD;
#pragma unroll
        for (int k = 0; k < HD; k++) s += av[k] * w[k];
        out[g * NC + t] = s;
    }
}

extern "C" void kernel_launch(void* const* d_in, const int* in_sizes, int n_in,
                              void* d_out, int out_size) {
    const float* x           = (const float*)d_in[0];
    const float* edge_a      = (const float*)d_in[1];
    const float* bond_w      = (const float*)d_in[2];
    const float* bond_b      = (const float*)d_in[3];
    const float* c1_rel_w    = (const float*)d_in[4];
    const float* c1_rel_b    = (const float*)d_in[5];
    const float* c1_root_w   = (const float*)d_in[6];
    const float* c2_rel_w    = (const float*)d_in[7];
    const float* c2_rel_b    = (const float*)d_in[8];
    const float* c2_root_w   = (const float*)d_in[9];
    const float* lin1_w      = (const float*)d_in[10];
    const float* lin1_b      = (const float*)d_in[11];
    const float* lin2_w      = (const float*)d_in[12];
    const float* lin2_b      = (const float*)d_in[13];
    const int*   edge_ix     = (const int*)d_in[14];   // int32
    const int*   batch       = (const int*)d_in[15];   // int32
    float* out = (float*)d_out;

    float* gmax1; cudaGetSymbolAddress((void**)&gmax1, g_max1);
    float* gmax2; cudaGetSymbolAddress((void**)&gmax2, g_max2);
    float* h1p;   cudaGetSymbolAddress((void**)&h1p,   g_h1);

    const int smem1 = (50 * 132 + 50 * 64) * 4;   // 39.2 KB
    const int smem2 = (64 * 132 + 64 * 64) * 4;   // 50.2 KB
    cudaFuncSetAttribute(k_conv_fused<50, true>,
                         cudaFuncAttributeMaxDynamicSharedMemorySize, smem1);
    cudaFuncSetAttribute(k_conv_fused<64, false>,
                         cudaFuncAttributeMaxDynamicSharedMemorySize, smem2);

    k_init0<<<512, 256>>>();
    k_hist<<<(Ee + 255) / 256, 256>>>(edge_ix);
    k_scan_block<<<NBLK, 256>>>();
    k_scan_top<<<1, 512>>>();
    k_scan_add<<<NBLK, 256>>>();
    k_permute<<<(Ee + 255) / 256, 256>>>(edge_ix, edge_a, bond_w, bond_b);
    k_conv_fused<50, true><<<(Nn + 127) / 128, 512, smem1>>>(
        x, c1_rel_w, c1_rel_b, c1_root_w, batch, gmax1);
    k_conv_fused<64, false><<<(Nn + 127) / 128, 512, smem2>>>(
        h1p, c2_rel_w, c2_rel_b, c2_root_w, batch, gmax2);
    k_head<<<NG, 128>>>(lin1_w, lin1_b, lin2_w, lin2_b, out);
}

// round 5
// speedup vs baseline: 2.3496x; 1.1043x over previous
#include <cuda_runtime.h>
#include <cuda_bf16.h>

#define Nn   100000
#define Ee   1600000
#define FIN  50
#define HD   64
#define NG   512
#define NC   10
#define BOND 10
#define NBLK 391          // ceil(Nn/256)

// ---------------- scratch (device globals) ----------------
__device__ __align__(16) int   g_deg[Nn];
__device__ __align__(16) int   g_rowx[Nn];
__device__ __align__(16) int   g_bsum[NBLK];
__device__ __align__(16) int   g_topex[512];
__device__ __align__(16) int   g_row[Nn + 1];    // CSR row starts
__device__ __align__(16) int   g_cur[Nn];        // placement cursors
__device__ __align__(16) int2  g_epk[Ee];        // packed (src, ew-bits), dst-sorted
__device__ __align__(16) float g_h1[Nn * HD];    // relu(h1)
__device__ __align__(16) float g_max1[NG * HD];
__device__ __align__(16) float g_max2[NG * HD];
__device__ __align__(16) float g_sumv[NG * HD];
__device__ __align__(16) float g_cnt[NG];

__device__ __forceinline__ void atomicMaxF(float* a, float v) {
    if (v >= 0.f) atomicMax((int*)a, __float_as_int(v));
    else          atomicMin((unsigned int*)a, __float_as_uint(v));
}

// ---------------- init ----------------
__global__ void k_init0() {
    int i = blockIdx.x * blockDim.x + threadIdx.x;
    int stride = gridDim.x * blockDim.x;
    for (int j = i; j < Nn; j += stride) g_deg[j] = 0;
    float ninf = __int_as_float(0xff800000);
    for (int j = i; j < NG * HD; j += stride) {
        g_sumv[j] = 0.f; g_max1[j] = ninf; g_max2[j] = ninf;
    }
    for (int j = i; j < NG; j += stride) g_cnt[j] = 0.f;
}

// ---------------- histogram of dst ----------------
__global__ void k_hist(const int* __restrict__ ei) {
    int e = blockIdx.x * blockDim.x + threadIdx.x;
    if (e >= Ee) return;
    atomicAdd(&g_deg[ei[Ee + e]], 1);
}

// ---------------- hierarchical exclusive scan ----------------
__global__ void k_scan_block() {
    __shared__ int s[256];
    int t = threadIdx.x;
    int i = blockIdx.x * 256 + t;
    int v = (i < Nn) ? g_deg[i] : 0;
    s[t] = v;
    __syncthreads();
#pragma unroll
    for (int off = 1; off < 256; off <<= 1) {
        int x = (t >= off) ? s[t - off] : 0;
        __syncthreads();
        s[t] += x;
        __syncthreads();
    }
    if (i < Nn) g_rowx[i] = s[t] - v;
    if (t == 255) g_bsum[blockIdx.x] = s[t];
}

__global__ void k_scan_top() {
    __shared__ int s[512];
    int t = threadIdx.x;
    int v = (t < NBLK) ? g_bsum[t] : 0;
    s[t] = v;
    __syncthreads();
#pragma unroll
    for (int off = 1; off < 512; off <<= 1) {
        int x = (t >= off) ? s[t - off] : 0;
        __syncthreads();
        s[t] += x;
        __syncthreads();
    }
    g_topex[t] = s[t] - v;
}

__global__ void k_scan_add() {
    int i = blockIdx.x * blockDim.x + threadIdx.x;
    if (i == 0) g_row[Nn] = Ee;
    if (i >= Nn) return;
    int rs = g_rowx[i] + g_topex[i >> 8];
    g_row[i] = rs;
    g_cur[i] = rs;
}

// ---------------- permute: ew inline, place (src, ew) sorted by dst ------------
__global__ void k_permute(const int* __restrict__ ei,
                          const float* __restrict__ ea,
                          const float* __restrict__ bw,
                          const float* __restrict__ bb) {
    int e = blockIdx.x * blockDim.x + threadIdx.x;
    if (e >= Ee) return;
    const float2* row = (const float2*)(ea + (size_t)e * BOND);
    float w = bb[0];
#pragma unroll
    for (int j = 0; j < BOND / 2; j++) {
        float2 v = row[j];
        w += v.x * __ldg(&bw[2 * j]) + v.y * __ldg(&bw[2 * j + 1]);
    }
    int s = ei[e];
    int d = ei[Ee + e];
    int pos = atomicAdd(&g_cur[d], 1);
    g_epk[pos] = make_int2(s, __float_as_int(w));
}

// ============== fused conv layer ==============
// 512 threads, 128-node tile. Phase A: warp-per-8-nodes CSR gather-reduce with
// 4-way unrolled edge loop (4 independent accumulators -> MLP ~8).
// Phase B: 2 outs x 8 nodes/thread register-blocked GEMM (rel half, then root
// half after restage). Epilogue: run-length pooling + (conv1) h1 store.
template<int KH, bool IS_CONV1>
__global__ __launch_bounds__(512, 2)
void k_conv_fused(const float* __restrict__ src,     // x (conv1) or g_h1 (conv2)
                  const float* __restrict__ relw,
                  const float* __restrict__ relb,
                  const float* __restrict__ rootw,
                  const int* __restrict__ batch,
                  float* __restrict__ gmax) {
    constexpr int NL = KH / 2;
    extern __shared__ float smem[];
    float* vs = smem;                 // [KH][132]
    float* ws = smem + KH * 132;      // [KH][64]

    int tid  = threadIdx.x;
    int lane = tid & 31;
    int wid  = tid >> 5;              // 0..15
    int o    = lane;                  // outputs o, o+32
    int slot = wid;
    int base = blockIdx.x * 128;
    bool act = (lane < NL);

    // ---- stage rel weights ----
    for (int idx = tid; idx < KH * 64; idx += 512) {
        int oo = idx & 63, k = idx >> 6;
        ws[k * 64 + oo] = relw[oo * KH + k];
    }

    // ---- phase A: unrolled gather-reduce into vs (transposed) ----
#pragma unroll 1
    for (int j = 0; j < 8; j++) {
        int n = base + wid * 8 + j;
        float2 a0 = make_float2(0.f, 0.f), a1 = a0, a2 = a0, a3 = a0;
        if (n < Nn) {
            int e  = g_row[n];
            int e1 = g_row[n + 1];
#pragma unroll 1
            for (; e + 4 <= e1; e += 4) {
                int2 p0 = __ldg(&g_epk[e]);
                int2 p1 = __ldg(&g_epk[e + 1]);
                int2 p2 = __ldg(&g_epk[e + 2]);
                int2 p3 = __ldg(&g_epk[e + 3]);
                if (act) {
                    float2 v0 = ((const float2*)(src + (size_t)p0.x * KH))[lane];
                    float2 v1 = ((const float2*)(src + (size_t)p1.x * KH))[lane];
                    float2 v2 = ((const float2*)(src + (size_t)p2.x * KH))[lane];
                    float2 v3 = ((const float2*)(src + (size_t)p3.x * KH))[lane];
                    float w0 = __int_as_float(p0.y), w1 = __int_as_float(p1.y);
                    float w2 = __int_as_float(p2.y), w3 = __int_as_float(p3.y);
                    a0.x += w0 * v0.x; a0.y += w0 * v0.y;
                    a1.x += w1 * v1.x; a1.y += w1 * v1.y;
                    a2.x += w2 * v2.x; a2.y += w2 * v2.y;
                    a3.x += w3 * v3.x; a3.y += w3 * v3.y;
                }
            }
#pragma unroll 1
            for (; e < e1; e++) {
                int2 p = __ldg(&g_epk[e]);
                if (act) {
                    float2 v = ((const float2*)(src + (size_t)p.x * KH))[lane];
                    float w = __int_as_float(p.y);
                    a0.x += w * v.x; a0.y += w * v.y;
                }
            }
        }
        if (act) {
            int nn = wid * 8 + j;
            vs[(2 * lane) * 132 + nn]     = (a0.x + a1.x) + (a2.x + a3.x);
            vs[(2 * lane + 1) * 132 + nn] = (a0.y + a1.y) + (a2.y + a3.y);
        }
    }
    __syncthreads();

    // ---- phase B chunk 1: rel part ----
    float acc0[8], acc1[8];
    float b0 = relb[o], b1 = relb[o + 32];
#pragma unroll
    for (int j = 0; j < 8; j++) { acc0[j] = b0; acc1[j] = b1; }

#pragma unroll 8
    for (int k = 0; k < KH; k++) {
        float w0 = ws[k * 64 + o];
        float w1 = ws[k * 64 + o + 32];
        float4 a = *(const float4*)&vs[k * 132 + slot * 8];
        float4 b = *(const float4*)&vs[k * 132 + slot * 8 + 4];
        acc0[0] += w0 * a.x; acc1[0] += w1 * a.x;
        acc0[1] += w0 * a.y; acc1[1] += w1 * a.y;
        acc0[2] += w0 * a.z; acc1[2] += w1 * a.z;
        acc0[3] += w0 * a.w; acc1[3] += w1 * a.w;
        acc0[4] += w0 * b.x; acc1[4] += w1 * b.x;
        acc0[5] += w0 * b.y; acc1[5] += w1 * b.y;
        acc0[6] += w0 * b.z; acc1[6] += w1 * b.z;
        acc0[7] += w0 * b.w; acc1[7] += w1 * b.w;
    }
    __syncthreads();

    // ---- restage: vs <- src rows (coalesced), ws <- root weights ----
    for (int idx = tid; idx < 128 * NL; idx += 512) {
        int n = idx / NL, i = idx % NL;
        float2 v = make_float2(0.f, 0.f);
        if (base + n < Nn)
            v = ((const float2*)(src + (size_t)(base + n) * KH))[i];
        vs[(2 * i) * 132 + n]     = v.x;
        vs[(2 * i + 1) * 132 + n] = v.y;
    }
    for (int idx = tid; idx < KH * 64; idx += 512) {
        int oo = idx & 63, k = idx >> 6;
        ws[k * 64 + oo] = rootw[oo * KH + k];
    }
    __syncthreads();

    // ---- phase B chunk 2: root part ----
#pragma unroll 8
    for (int k = 0; k < KH; k++) {
        float w0 = ws[k * 64 + o];
        float w1 = ws[k * 64 + o + 32];
        float4 a = *(const float4*)&vs[k * 132 + slot * 8];
        float4 b = *(const float4*)&vs[k * 132 + slot * 8 + 4];
        acc0[0] += w0 * a.x; acc1[0] += w1 * a.x;
        acc0[1] += w0 * a.y; acc1[1] += w1 * a.y;
        acc0[2] += w0 * a.z; acc1[2] += w1 * a.z;
        acc0[3] += w0 * a.w; acc1[3] += w1 * a.w;
        acc0[4] += w0 * b.x; acc1[4] += w1 * b.x;
        acc0[5] += w0 * b.y; acc1[5] += w1 * b.y;
        acc0[6] += w0 * b.z; acc1[6] += w1 * b.z;
        acc0[7] += w0 * b.w; acc1[7] += w1 * b.w;
    }

    // ---- epilogue: run-length pooling + (conv1) h1 store ----
    float ninf = __int_as_float(0xff800000);
    float rs0 = 0.f, rs1 = 0.f, rm0 = ninf, rm1 = ninf;
    int runb = -1, runcnt = 0;
    int nb = base + slot * 8;
#pragma unroll 1
    for (int j = 0; j < 8; j++) {
        int n = nb + j;
        if (n >= Nn) break;
        float s0 = acc0[j], s1 = acc1[j];
        int b = batch[n];
        if (b != runb) {
            if (runb >= 0) {
                atomicAdd(&g_sumv[runb * HD + o], rs0);
                atomicAdd(&g_sumv[runb * HD + o + 32], rs1);
                atomicMaxF(&gmax[runb * HD + o], rm0);
                atomicMaxF(&gmax[runb * HD + o + 32], rm1);
                if (IS_CONV1 && o == 0) atomicAdd(&g_cnt[runb], (float)runcnt);
            }
            runb = b; rs0 = 0.f; rs1 = 0.f; rm0 = ninf; rm1 = ninf; runcnt = 0;
        }
        rs0 += s0; rs1 += s1;
        rm0 = fmaxf(rm0, s0); rm1 = fmaxf(rm1, s1);
        runcnt++;
        if (IS_CONV1) {
            g_h1[(size_t)n * HD + o]      = fmaxf(s0, 0.f);
            g_h1[(size_t)n * HD + o + 32] = fmaxf(s1, 0.f);
        }
    }
    if (runb >= 0) {
        atomicAdd(&g_sumv[runb * HD + o], rs0);
        atomicAdd(&g_sumv[runb * HD + o + 32], rs1);
        atomicMaxF(&gmax[runb * HD + o], rm0);
        atomicMaxF(&gmax[runb * HD + o + 32], rm1);
        if (IS_CONV1 && o == 0) atomicAdd(&g_cnt[runb], (float)runcnt);
    }
}

// ---------------- head ----------------
__global__ void k_head(const float* __restrict__ l1w, const float* __restrict__ l1b,
                       const float* __restrict__ l2w, const float* __restrict__ l2b,
                       float* __restrict__ out) {
    int g = blockIdx.x;
    __shared__ float gv[2 * HD];
    __shared__ float av[HD];
    int t = threadIdx.x;   // 128
    if (t < HD) {
        gv[t] = g_max1[g * HD + t] + g_max2[g * HD + t];
    } else {
        float c = g_cnt[g];
        gv[t] = g_sumv[g * HD + (t - HD)] / fmaxf(c, 1.0f);
    }
    __syncthreads();
    if (t < HD) {
        float s = l1b[t];
        const float* w = l1w + t * 2 * HD;
#pragma unroll
        for (int k = 0; k < 2 * HD; k++) s += gv[k] * w[k];
        av[t] = fmaxf(s, 0.f);
    }
    __syncthreads();
    if (t < NC) {
        float s = l2b[t];
        const float* w = l2w + t * HD;
#pragma unroll
        for (int k = 0; k < HD; k++) s += av[k] * w[k];
        out[g * NC + t] = s;
    }
}

extern "C" void kernel_launch(void* const* d_in, const int* in_sizes, int n_in,
                              void* d_out, int out_size) {
    const float* x           = (const float*)d_in[0];
    const float* edge_a      = (const float*)d_in[1];
    const float* bond_w      = (const float*)d_in[2];
    const float* bond_b      = (const float*)d_in[3];
    const float* c1_rel_w    = (const float*)d_in[4];
    const float* c1_rel_b    = (const float*)d_in[5];
    const float* c1_root_w   = (const float*)d_in[6];
    const float* c2_rel_w    = (const float*)d_in[7];
    const float* c2_rel_b    = (const float*)d_in[8];
    const float* c2_root_w   = (const float*)d_in[9];
    const float* lin1_w      = (const float*)d_in[10];
    const float* lin1_b      = (const float*)d_in[11];
    const float* lin2_w      = (const float*)d_in[12];
    const float* lin2_b      = (const float*)d_in[13];
    const int*   edge_ix     = (const int*)d_in[14];   // int32
    const int*   batch       = (const int*)d_in[15];   // int32
    float* out = (float*)d_out;

    float* gmax1; cudaGetSymbolAddress((void**)&gmax1, g_max1);
    float* gmax2; cudaGetSymbolAddress((void**)&gmax2, g_max2);
    float* h1p;   cudaGetSymbolAddress((void**)&h1p,   g_h1);

    const int smem1 = (50 * 132 + 50 * 64) * 4;   // 39.2 KB
    const int smem2 = (64 * 132 + 64 * 64) * 4;   // 50.2 KB
    cudaFuncSetAttribute(k_conv_fused<50, true>,
                         cudaFuncAttributeMaxDynamicSharedMemorySize, smem1);
    cudaFuncSetAttribute(k_conv_fused<64, false>,
                         cudaFuncAttributeMaxDynamicSharedMemorySize, smem2);

    k_init0<<<512, 256>>>();
    k_hist<<<(Ee + 255) / 256, 256>>>(edge_ix);
    k_scan_block<<<NBLK, 256>>>();
    k_scan_top<<<1, 512>>>();
    k_scan_add<<<NBLK, 256>>>();
    k_permute<<<(Ee + 255) / 256, 256>>>(edge_ix, edge_a, bond_w, bond_b);
    k_conv_fused<50, true><<<(Nn + 127) / 128, 512, smem1>>>(
        x, c1_rel_w, c1_rel_b, c1_root_w, batch, gmax1);
    k_conv_fused<64, false><<<(Nn + 127) / 128, 512, smem2>>>(
        h1p, c2_rel_w, c2_rel_b, c2_root_w, batch, gmax2);
    k_head<<<NG, 128>>>(lin1_w, lin1_b, lin2_w, lin2_b, out);
}

// round 6
// speedup vs baseline: 2.4681x; 1.0504x over previous
#include <cuda_runtime.h>
#include <cuda_bf16.h>

#define Nn   100000
#define Ee   1600000
#define FIN  50
#define HD   64
#define NG   512
#define NC   10
#define BOND 10
#define NBLK 391          // ceil(Nn/256)

// ---------------- scratch (device globals) ----------------
__device__ __align__(16) int   g_deg[Nn];
__device__ __align__(16) int   g_rowx[Nn];
__device__ __align__(16) int   g_bsum[NBLK];
__device__ __align__(16) int   g_row[Nn + 1];    // CSR row starts
__device__ __align__(16) int   g_cur[Nn];        // placement cursors
__device__ __align__(16) int2  g_epk[Ee];        // packed (src, ew-bits), dst-sorted
__device__ __align__(16) float g_h1[Nn * HD];    // relu(h1)
__device__ __align__(16) float g_max1[NG * HD];
__device__ __align__(16) float g_max2[NG * HD];
__device__ __align__(16) float g_sumv[NG * HD];
__device__ __align__(16) float g_cnt[NG];

__device__ __forceinline__ void atomicMaxF(float* a, float v) {
    if (v >= 0.f) atomicMax((int*)a, __float_as_int(v));
    else          atomicMin((unsigned int*)a, __float_as_uint(v));
}

// ---------------- init ----------------
__global__ void k_init0() {
    int i = blockIdx.x * blockDim.x + threadIdx.x;
    int stride = gridDim.x * blockDim.x;
    for (int j = i; j < Nn; j += stride) g_deg[j] = 0;
    float ninf = __int_as_float(0xff800000);
    for (int j = i; j < NG * HD; j += stride) {
        g_sumv[j] = 0.f; g_max1[j] = ninf; g_max2[j] = ninf;
    }
    for (int j = i; j < NG; j += stride) g_cnt[j] = 0.f;
}

// ---------------- histogram of dst ----------------
__global__ void k_hist(const int* __restrict__ ei) {
    int e = blockIdx.x * blockDim.x + threadIdx.x;
    if (e >= Ee) return;
    atomicAdd(&g_deg[ei[Ee + e]], 1);
}

// ---------------- scan pass 1: per-block exclusive scan ----------------
__global__ void k_scan_block() {
    __shared__ int s[256];
    int t = threadIdx.x;
    int i = blockIdx.x * 256 + t;
    int v = (i < Nn) ? g_deg[i] : 0;
    s[t] = v;
    __syncthreads();
#pragma unroll
    for (int off = 1; off < 256; off <<= 1) {
        int x = (t >= off) ? s[t - off] : 0;
        __syncthreads();
        s[t] += x;
        __syncthreads();
    }
    if (i < Nn) g_rowx[i] = s[t] - v;
    if (t == 255) g_bsum[blockIdx.x] = s[t];
}

// ---------------- scan pass 2: redundant top-prefix + add (merged) -------------
__global__ void k_scan_add2() {
    __shared__ int sh[256];
    int bid = blockIdx.x, t = threadIdx.x;
    int partial = 0;
    for (int j = t; j < bid; j += 256) partial += g_bsum[j];
    sh[t] = partial;
    __syncthreads();
#pragma unroll
    for (int off = 128; off > 0; off >>= 1) {
        if (t < off) sh[t] += sh[t + off];
        __syncthreads();
    }
    int topex = sh[0];
    if (bid == 0 && t == 0) g_row[Nn] = Ee;
    int i = bid * 256 + t;
    if (i < Nn) {
        int rs = g_rowx[i] + topex;
        g_row[i] = rs;
        g_cur[i] = rs;
    }
}

// ---------------- permute: ew inline, place (src, ew) sorted by dst ------------
__global__ void k_permute(const int* __restrict__ ei,
                          const float* __restrict__ ea,
                          const float* __restrict__ bw,
                          const float* __restrict__ bb) {
    int e = blockIdx.x * blockDim.x + threadIdx.x;
    if (e >= Ee) return;
    const float2* row = (const float2*)(ea + (size_t)e * BOND);
    float w = bb[0];
#pragma unroll
    for (int j = 0; j < BOND / 2; j++) {
        float2 v = row[j];
        w += v.x * __ldg(&bw[2 * j]) + v.y * __ldg(&bw[2 * j + 1]);
    }
    int s = ei[e];
    int d = ei[Ee + e];
    int pos = atomicAdd(&g_cur[d], 1);
    g_epk[pos] = make_int2(s, __float_as_int(w));
}

// ============== fused conv layer ==============
// 512 threads, 128-node tile.
// Phase A: warp-per-8-nodes gather-reduce. Edge records fetched ONCE per node
// via one coalesced lane-indexed LDG.64 (deg<=32 covers >99.99% of nodes) and
// broadcast via shfl; row gathers 4-way unrolled with independent accumulators.
// Phase B: 2 outs x 8 nodes/thread register-blocked GEMM (rel, restage, root).
// Epilogue: run-length pooling + (conv1) relu h1 store.
template<int KH, bool IS_CONV1>
__global__ __launch_bounds__(512, 2)
void k_conv_fused(const float* __restrict__ src,     // x (conv1) or g_h1 (conv2)
                  const float* __restrict__ relw,
                  const float* __restrict__ relb,
                  const float* __restrict__ rootw,
                  const int* __restrict__ batch,
                  float* __restrict__ gmax) {
    constexpr int NL = KH / 2;
    extern __shared__ float smem[];
    float*  vs  = smem;                          // [KH][132]
    float2* ws2 = (float2*)(smem + KH * 132);    // [KH][32] pairs (o, o+32)

    int tid  = threadIdx.x;
    int lane = tid & 31;
    int wid  = tid >> 5;              // 0..15
    int o    = lane;                  // outputs o, o+32
    int slot = wid;
    int base = blockIdx.x * 128;
    bool act = (lane < NL);

    // ---- stage rel weights as (o, o+32) pairs ----
    for (int idx = tid; idx < KH * 32; idx += 512) {
        int oo = idx & 31, k = idx >> 5;
        ws2[k * 32 + oo] = make_float2(relw[oo * KH + k],
                                       relw[(oo + 32) * KH + k]);
    }

    // ---- phase A ----
#pragma unroll 1
    for (int j = 0; j < 8; j++) {
        int n = base + wid * 8 + j;
        float2 a0 = make_float2(0.f, 0.f), a1 = a0, a2 = a0, a3 = a0;
        if (n < Nn) {
            int e0  = g_row[n];
            int deg = g_row[n + 1] - e0;
            int dc  = deg < 32 ? deg : 32;
            int2 pk = make_int2(0, 0);
            if (lane < deg) pk = __ldg(&g_epk[e0 + lane]);
            int i = 0;
#pragma unroll 1
            for (; i + 4 <= dc; i += 4) {
                int   s0 = __shfl_sync(0xffffffffu, pk.x, i);
                float w0 = __int_as_float(__shfl_sync(0xffffffffu, pk.y, i));
                int   s1 = __shfl_sync(0xffffffffu, pk.x, i + 1);
                float w1 = __int_as_float(__shfl_sync(0xffffffffu, pk.y, i + 1));
                int   s2 = __shfl_sync(0xffffffffu, pk.x, i + 2);
                float w2 = __int_as_float(__shfl_sync(0xffffffffu, pk.y, i + 2));
                int   s3 = __shfl_sync(0xffffffffu, pk.x, i + 3);
                float w3 = __int_as_float(__shfl_sync(0xffffffffu, pk.y, i + 3));
                if (act) {
                    float2 v0 = ((const float2*)(src + (size_t)s0 * KH))[lane];
                    float2 v1 = ((const float2*)(src + (size_t)s1 * KH))[lane];
                    float2 v2 = ((const float2*)(src + (size_t)s2 * KH))[lane];
                    float2 v3 = ((const float2*)(src + (size_t)s3 * KH))[lane];
                    a0.x += w0 * v0.x; a0.y += w0 * v0.y;
                    a1.x += w1 * v1.x; a1.y += w1 * v1.y;
                    a2.x += w2 * v2.x; a2.y += w2 * v2.y;
                    a3.x += w3 * v3.x; a3.y += w3 * v3.y;
                }
            }
#pragma unroll 1
            for (; i < dc; i++) {
                int   s = __shfl_sync(0xffffffffu, pk.x, i);
                float w = __int_as_float(__shfl_sync(0xffffffffu, pk.y, i));
                if (act) {
                    float2 v = ((const float2*)(src + (size_t)s * KH))[lane];
                    a0.x += w * v.x; a0.y += w * v.y;
                }
            }
            // rare overflow (deg > 32)
#pragma unroll 1
            for (int e = e0 + 32; e < e0 + deg; e++) {
                int2 p = __ldg(&g_epk[e]);
                if (act) {
                    float2 v = ((const float2*)(src + (size_t)p.x * KH))[lane];
                    float w = __int_as_float(p.y);
                    a0.x += w * v.x; a0.y += w * v.y;
                }
            }
        }
        if (act) {
            int nn = wid * 8 + j;
            vs[(2 * lane) * 132 + nn]     = (a0.x + a1.x) + (a2.x + a3.x);
            vs[(2 * lane + 1) * 132 + nn] = (a0.y + a1.y) + (a2.y + a3.y);
        }
    }
    __syncthreads();

    // ---- phase B chunk 1: rel part ----
    float acc0[8], acc1[8];
    float b0 = relb[o], b1 = relb[o + 32];
#pragma unroll
    for (int j = 0; j < 8; j++) { acc0[j] = b0; acc1[j] = b1; }

#pragma unroll 8
    for (int k = 0; k < KH; k++) {
        float2 w = ws2[k * 32 + o];
        float4 a = *(const float4*)&vs[k * 132 + slot * 8];
        float4 b = *(const float4*)&vs[k * 132 + slot * 8 + 4];
        acc0[0] += w.x * a.x; acc1[0] += w.y * a.x;
        acc0[1] += w.x * a.y; acc1[1] += w.y * a.y;
        acc0[2] += w.x * a.z; acc1[2] += w.y * a.z;
        acc0[3] += w.x * a.w; acc1[3] += w.y * a.w;
        acc0[4] += w.x * b.x; acc1[4] += w.y * b.x;
        acc0[5] += w.x * b.y; acc1[5] += w.y * b.y;
        acc0[6] += w.x * b.z; acc1[6] += w.y * b.z;
        acc0[7] += w.x * b.w; acc1[7] += w.y * b.w;
    }
    __syncthreads();

    // ---- restage: vs <- src rows (coalesced), ws <- root weights ----
    for (int idx = tid; idx < 128 * NL; idx += 512) {
        int n = idx / NL, i = idx % NL;
        float2 v = make_float2(0.f, 0.f);
        if (base + n < Nn)
            v = ((const float2*)(src + (size_t)(base + n) * KH))[i];
        vs[(2 * i) * 132 + n]     = v.x;
        vs[(2 * i + 1) * 132 + n] = v.y;
    }
    for (int idx = tid; idx < KH * 32; idx += 512) {
        int oo = idx & 31, k = idx >> 5;
        ws2[k * 32 + oo] = make_float2(rootw[oo * KH + k],
                                       rootw[(oo + 32) * KH + k]);
    }
    __syncthreads();

    // ---- phase B chunk 2: root part ----
#pragma unroll 8
    for (int k = 0; k < KH; k++) {
        float2 w = ws2[k * 32 + o];
        float4 a = *(const float4*)&vs[k * 132 + slot * 8];
        float4 b = *(const float4*)&vs[k * 132 + slot * 8 + 4];
        acc0[0] += w.x * a.x; acc1[0] += w.y * a.x;
        acc0[1] += w.x * a.y; acc1[1] += w.y * a.y;
        acc0[2] += w.x * a.z; acc1[2] += w.y * a.z;
        acc0[3] += w.x * a.w; acc1[3] += w.y * a.w;
        acc0[4] += w.x * b.x; acc1[4] += w.y * b.x;
        acc0[5] += w.x * b.y; acc1[5] += w.y * b.y;
        acc0[6] += w.x * b.z; acc1[6] += w.y * b.z;
        acc0[7] += w.x * b.w; acc1[7] += w.y * b.w;
    }

    // ---- epilogue: run-length pooling + (conv1) h1 store ----
    float ninf = __int_as_float(0xff800000);
    float rs0 = 0.f, rs1 = 0.f, rm0 = ninf, rm1 = ninf;
    int runb = -1, runcnt = 0;
    int nb = base + slot * 8;
#pragma unroll 1
    for (int j = 0; j < 8; j++) {
        int n = nb + j;
        if (n >= Nn) break;
        float s0 = acc0[j], s1 = acc1[j];
        int b = batch[n];
        if (b != runb) {
            if (runb >= 0) {
                atomicAdd(&g_sumv[runb * HD + o], rs0);
                atomicAdd(&g_sumv[runb * HD + o + 32], rs1);
                atomicMaxF(&gmax[runb * HD + o], rm0);
                atomicMaxF(&gmax[runb * HD + o + 32], rm1);
                if (IS_CONV1 && o == 0) atomicAdd(&g_cnt[runb], (float)runcnt);
            }
            runb = b; rs0 = 0.f; rs1 = 0.f; rm0 = ninf; rm1 = ninf; runcnt = 0;
        }
        rs0 += s0; rs1 += s1;
        rm0 = fmaxf(rm0, s0); rm1 = fmaxf(rm1, s1);
        runcnt++;
        if (IS_CONV1) {
            g_h1[(size_t)n * HD + o]      = fmaxf(s0, 0.f);
            g_h1[(size_t)n * HD + o + 32] = fmaxf(s1, 0.f);
        }
    }
    if (runb >= 0) {
        atomicAdd(&g_sumv[runb * HD + o], rs0);
        atomicAdd(&g_sumv[runb * HD + o + 32], rs1);
        atomicMaxF(&gmax[runb * HD + o], rm0);
        atomicMaxF(&gmax[runb * HD + o + 32], rm1);
        if (IS_CONV1 && o == 0) atomicAdd(&g_cnt[runb], (float)runcnt);
    }
}

// ---------------- head ----------------
__global__ void k_head(const float* __restrict__ l1w, const float* __restrict__ l1b,
                       const float* __restrict__ l2w, const float* __restrict__ l2b,
                       float* __restrict__ out) {
    int g = blockIdx.x;
    __shared__ float gv[2 * HD];
    __shared__ float av[HD];
    int t = threadIdx.x;   // 128
    if (t < HD) {
        gv[t] = g_max1[g * HD + t] + g_max2[g * HD + t];
    } else {
        float c = g_cnt[g];
        gv[t] = g_sumv[g * HD + (t - HD)] / fmaxf(c, 1.0f);
    }
    __syncthreads();
    if (t < HD) {
        float s = l1b[t];
        const float* w = l1w + t * 2 * HD;
#pragma unroll
        for (int k = 0; k < 2 * HD; k++) s += gv[k] * w[k];
        av[t] = fmaxf(s, 0.f);
    }
    __syncthreads();
    if (t < NC) {
        float s = l2b[t];
        const float* w = l2w + t * HD;
#pragma unroll
        for (int k = 0; k < HD; k++) s += av[k] * w[k];
        out[g * NC + t] = s;
    }
}

extern "C" void kernel_launch(void* const* d_in, const int* in_sizes, int n_in,
                              void* d_out, int out_size) {
    const float* x           = (const float*)d_in[0];
    const float* edge_a      = (const float*)d_in[1];
    const float* bond_w      = (const float*)d_in[2];
    const float* bond_b      = (const float*)d_in[3];
    const float* c1_rel_w    = (const float*)d_in[4];
    const float* c1_rel_b    = (const float*)d_in[5];
    const float* c1_root_w   = (const float*)d_in[6];
    const float* c2_rel_w    = (const float*)d_in[7];
    const float* c2_rel_b    = (const float*)d_in[8];
    const float* c2_root_w   = (const float*)d_in[9];
    const float* lin1_w      = (const float*)d_in[10];
    const float* lin1_b      = (const float*)d_in[11];
    const float* lin2_w      = (const float*)d_in[12];
    const float* lin2_b      = (const float*)d_in[13];
    const int*   edge_ix     = (const int*)d_in[14];   // int32
    const int*   batch       = (const int*)d_in[15];   // int32
    float* out = (float*)d_out;

    float* gmax1; cudaGetSymbolAddress((void**)&gmax1, g_max1);
    float* gmax2; cudaGetSymbolAddress((void**)&gmax2, g_max2);
    float* h1p;   cudaGetSymbolAddress((void**)&h1p,   g_h1);

    const int smem1 = (50 * 132 + 50 * 64) * 4;   // 39.2 KB
    const int smem2 = (64 * 132 + 64 * 64) * 4;   // 50.2 KB
    cudaFuncSetAttribute(k_conv_fused<50, true>,
                         cudaFuncAttributeMaxDynamicSharedMemorySize, smem1);
    cudaFuncSetAttribute(k_conv_fused<64, false>,
                         cudaFuncAttributeMaxDynamicSharedMemorySize, smem2);

    k_init0<<<512, 256>>>();
    k_hist<<<(Ee + 255) / 256, 256>>>(edge_ix);
    k_scan_block<<<NBLK, 256>>>();
    k_scan_add2<<<NBLK, 256>>>();
    k_permute<<<(Ee + 255) / 256, 256>>>(edge_ix, edge_a, bond_w, bond_b);
    k_conv_fused<50, true><<<(Nn + 127) / 128, 512, smem1>>>(
        x, c1_rel_w, c1_rel_b, c1_root_w, batch, gmax1);
    k_conv_fused<64, false><<<(Nn + 127) / 128, 512, smem2>>>(
        h1p, c2_rel_w, c2_rel_b, c2_root_w, batch, gmax2);
    k_head<<<NG, 128>>>(lin1_w, lin1_b, lin2_w, lin2_b, out);
}